// round 13
// baseline (speedup 1.0000x reference)
#include <cuda_runtime.h>
#include <cuda_fp16.h>
#include <cstdint>
#include <math.h>

#define BATCH 16
#define CHAN  256
#define TLEN  4096
#define NLAYERS 8
#define NCHUNK 8                         // 8 chunks of k=64
#define GUARD 128
#define PROWS (GUARD + TLEN)             // 4224 rows per plane
#define PLANE ((size_t)PROWS * 64)       // halfs per (b,kc) plane (64-ch rows)
#define XBUF  ((size_t)BATCH * 4 * PLANE)
#define NTILES 4096                      // per layer: 16 b x 32 T x 8 cb
#define TOT_TILES (NLAYERS * NTILES)

// ---------------- device scratch -------------------------------------------
__device__ __align__(128) __half g_xA[XBUF];
__device__ __align__(128) __half g_xB[XBUF];
// W: [l][chunk8][cb8][fg2][32cout][64k], 8-quad swizzled by cout
__device__ __align__(128) __half g_w2[(size_t)NLAYERS * 8 * 8 * 2 * 32 * 64];
// persistent-kernel sync state (re-zeroed each launch)
__device__ int g_cnt;
__device__ int g_ready[NLAYERS][BATCH][32];

// ---------------- smem geometry --------------------------------------------
#define STAGE_BYTES 24576
#define STAGE_TX    24576
#define NSTAGE 3
#define MB_OFF (NSTAGE * STAGE_BYTES)       // 73728; full[3] then empty[3]
#define SM_TOTAL (MB_OFF + 64)              // 73792 dynamic

// ---------------- asm helpers ----------------------------------------------
__device__ __forceinline__ uint32_t smem_u32(const void* p) {
    uint32_t a;
    asm("{ .reg .u64 t; cvta.to.shared.u64 t, %1; cvt.u32.u64 %0, t; }" : "=r"(a) : "l"(p));
    return a;
}
#define MBARRIER_INIT(mbar, cnt) \
    asm volatile("mbarrier.init.shared.b64 [%0], %1;" :: "r"((uint32_t)(mbar)), "r"((uint32_t)(cnt)) : "memory")
#define MBARRIER_EXPECT_TX(mbar, tx) \
    asm volatile("mbarrier.arrive.expect_tx.shared.b64 _, [%0], %1;" :: "r"((uint32_t)(mbar)), "r"((uint32_t)(tx)) : "memory")
#define MBARRIER_ARRIVE(mbar) \
    asm volatile("mbarrier.arrive.shared.b64 _, [%0];" :: "r"((uint32_t)(mbar)) : "memory")
#define MBARRIER_WAIT_PARITY(mbar, par) do { \
    uint32_t _m = (uint32_t)(mbar); uint32_t _p = (uint32_t)(par); uint32_t _d; \
    asm volatile("{\n\t.reg .pred p;\n\tmbarrier.try_wait.parity.acquire.cta.shared::cta.b64 p, [%1], %2;\n\tselp.b32 %0,1,0,p;\n\t}" \
        : "=r"(_d) : "r"(_m), "r"(_p) : "memory"); \
    if (!_d) { \
        asm volatile("{\n\t.reg .pred P1;\n\tWL_%=:\n\tmbarrier.try_wait.parity.acquire.cta.shared::cta.b64 P1, [%0], %1, 0x989680;\n\t@P1 bra.uni WD_%=;\n\tbra.uni WL_%=;\n\tWD_%=:\n\t}" \
            :: "r"(_m), "r"(_p) : "memory"); \
    } } while (0)
__device__ __forceinline__ void bulk_ld(uint32_t dst, const void* src, uint32_t bytes, uint32_t mbar) {
    asm volatile("cp.async.bulk.shared::cluster.global.mbarrier::complete_tx::bytes [%0], [%1], %2, [%3];"
                 :: "r"(dst), "l"(src), "r"(bytes), "r"(mbar) : "memory");
}
__device__ __forceinline__ void ldsm4(uint32_t* r, uint32_t addr) {
    asm volatile("ldmatrix.sync.aligned.m8n8.x4.shared.b16 {%0,%1,%2,%3}, [%4];"
                 : "=r"(r[0]), "=r"(r[1]), "=r"(r[2]), "=r"(r[3]) : "r"(addr));
}
__device__ __forceinline__ void mma16816(float* d, const uint32_t* a, const uint32_t* b) {
    asm volatile("mma.sync.aligned.m16n8k16.row.col.f32.f16.f16.f32 "
                 "{%0,%1,%2,%3}, {%4,%5,%6,%7}, {%8,%9}, {%0,%1,%2,%3};"
                 : "+f"(d[0]), "+f"(d[1]), "+f"(d[2]), "+f"(d[3])
                 : "r"(a[0]), "r"(a[1]), "r"(a[2]), "r"(a[3]), "r"(b[0]), "r"(b[1]));
}

// ---------------- prep kernels ---------------------------------------------
__global__ void init_sync() {
    int i = blockIdx.x * blockDim.x + threadIdx.x;
    if (i == 0) g_cnt = 0;
    if (i < NLAYERS * BATCH * 32)
        ((int*)g_ready)[i] = 0;
}

__global__ void zero_guards() {
    const size_t per = (size_t)BATCH * 4 * GUARD * 64;    // 524288
    size_t i = (size_t)blockIdx.x * blockDim.x + threadIdx.x;
    if (i >= 2 * per) return;
    int arr = (int)(i / per);
    size_t r = i % per;
    size_t plane_i = r / (GUARD * 64);
    size_t within  = r % (GUARD * 64);
    __half* p = arr ? g_xB : g_xA;
    p[plane_i * PLANE + within] = __ushort_as_half(0);
}

// w[l][cout][cin][tap] -> g_w2[l][ch][cb][fg][co32][64k], swizzle q^(cout&7)
__global__ void prep_weights(const float* __restrict__ fw, const float* __restrict__ gw) {
    int idx = blockIdx.x * blockDim.x + threadIdx.x;
    const int total = NLAYERS * 2 * 8 * 256 * 64;
    if (idx >= total) return;
    int kk   = idx & 63;
    int cout = (idx >> 6) & 255;
    int ch   = (idx >> 14) & 7;
    int fg   = (idx >> 17) & 1;
    int l    = idx >> 18;
    const float* w = fg ? gw : fw;
    int cin = (ch & 3) * 64 + kk;
    int tap = (ch < 4) ? 1 : 0;    // first 4 chunks = current sample
    float v = w[(((size_t)l * CHAN + cout) * CHAN + cin) * 2 + tap];
    int pos = (((kk >> 3) ^ (cout & 7)) << 3) | (kk & 7);
    size_t o = (((((size_t)l * 8 + ch) * 8 + (cout >> 5)) * 2 + fg) * 32 + (cout & 31)) * 64 + pos;
    g_w2[o] = __float2half_rn(v);
}

// ys [b][c][t] f32 -> swizzled planes, fp16
__global__ void prep_input(const float* __restrict__ ys) {
    __shared__ float tile[32][33];
    const int b  = blockIdx.z;
    const int c0 = blockIdx.y * 32;
    const int t0 = blockIdx.x * 32;
    const int tx = threadIdx.x, ty = threadIdx.y;   // 32 x 8
#pragma unroll
    for (int i = 0; i < 32; i += 8)
        tile[ty + i][tx] = ys[((size_t)b * CHAN + c0 + ty + i) * TLEN + t0 + tx];
    __syncthreads();
    const int kc = c0 >> 6;
    const int qbase = (c0 & 32) >> 3;    // 0 or 4
#pragma unroll
    for (int i = 0; i < 32; i += 8) {
        int t = t0 + ty + i;
        int pos = (((qbase + (tx >> 3)) ^ (t & 7)) << 3) | (tx & 7);
        size_t o = (((size_t)b * 4 + kc) * PROWS + GUARD + t) * 64 + pos;
        g_xA[o] = __float2half_rn(tile[tx][ty + i]);
    }
}

// ---------------- persistent fused kernel, tile-granular dependencies --------
__global__ __launch_bounds__(256, 3)
void wavenet_persistent(__half* __restrict__ xAp, __half* __restrict__ xBp,
                        const __half* __restrict__ Wbase,
                        const float* __restrict__ fbase,
                        const float* __restrict__ gbase,
                        float* __restrict__ Zout)
{
    extern __shared__ char smem[];
    __shared__ int s_tile;
    const uint32_t sb = smem_u32(smem);
    const int tid  = threadIdx.x;
    const int wid  = tid >> 5;
    const int lane = tid & 31;

    if (tid == 0) {
#pragma unroll
        for (int s = 0; s < NSTAGE; ++s) {
            MBARRIER_INIT(sb + MB_OFF + s * 8, 1);            // full: tx-based
            MBARRIER_INIT(sb + MB_OFF + 24 + s * 8, 8);       // empty: 8 warp arrivals
        }
    }
    __syncthreads();

    // ---- loop-invariant ldsm addressing ----
    const int m0 = (wid & 3) * 32;       // t within tile
    const int n0 = (wid >> 2) * 16;      // cout within tile (0 or 16)
    const int a_row = lane & 15;
    const uint32_t a_q0  = (uint32_t)(lane >> 4);
    const int b_row = ((lane >> 4) * 8) + (lane & 7);
    const uint32_t b_q0  = (uint32_t)((lane >> 3) & 1);
    const uint32_t aoff0 = (uint32_t)((m0 + a_row) * 128);
    const uint32_t aoff1 = aoff0 + 16 * 128;
    const uint32_t boff  = (uint32_t)((n0 + b_row) * 128);
    uint32_t qbv[4];
#pragma unroll
    for (int ks = 0; ks < 4; ++ks)
        qbv[ks] = (((uint32_t)(ks * 2) + b_q0) ^ (uint32_t)(b_row & 7)) * 16;

    // rolling pipeline state (continuous across tiles and layers)
    int sC = 0, fC = 0;        // consume: stage, phase
    int sI = 0, fI = 0;        // issue:   stage, phase
    int issued = 0;

    while (true) {
        // ---- grab next tile (layer-major order) + dependency spin ----------
        if (tid == 0) {
            int id = atomicAdd(&g_cnt, 1);
            s_tile = id;
            if (id < TOT_TILES) {
                int l      = id >> 12;
                int within = id & 4095;
                if (l > 0) {
                    int T = (within >> 3) & 31;
                    int b = within >> 8;
                    volatile int* r0 = &g_ready[l - 1][b][T];
                    while (*r0 < 8) __nanosleep(64);
                    if (T > 0) {
                        volatile int* r1 = &g_ready[l - 1][b][T - 1];
                        while (*r1 < 8) __nanosleep(64);
                    }
                }
                __threadfence();   // acquire: producers' stores visible
            }
        }
        __syncthreads();
        const int id = s_tile;
        if (id >= TOT_TILES) break;

        const int l      = id >> 12;
        const int within = id & 4095;
        const int cb     = within & 7;
        const int T      = (within >> 3) & 31;
        const int b      = within >> 8;
        const int t0     = T << 7;
        const int cout0  = cb << 5;
        const int dil    = 1 << l;
        const int first  = (l == 0);

        const __half* X = (l & 1) ? xBp : xAp;
        __half*       Y = (l & 1) ? xAp : xBp;
        const __half* Wl = Wbase + (size_t)l * 8 * 8 * 2 * 32 * 64;
        const float*  fb = fbase + l * CHAN;
        const float*  gb = gbase + l * CHAN;
        const __half* Xb = X + (size_t)b * 4 * PLANE;

#define ISSUE_CC(CC) do {                                                        \
        uint32_t _mb = sb + MB_OFF + sI * 8;                                     \
        uint32_t _st = sb + sI * STAGE_BYTES;                                    \
        int _sh = ((CC) >= 4) ? dil : 0;                                         \
        int _kc = (CC) & 3;                                                      \
        MBARRIER_EXPECT_TX(_mb, STAGE_TX);                                       \
        bulk_ld(_st,         Xb + ((size_t)_kc * PROWS + GUARD + t0 - _sh) * 64, 16384, _mb); \
        bulk_ld(_st + 16384, Wl + ((size_t)(CC) * 8 + cb) * 4096, 8192, _mb);    \
    } while (0)

        // prologue: 3 chunk issues (tid 0), counters advance uniformly
#pragma unroll
        for (int j = 0; j < 3; ++j) {
            if (tid == 0) {
                if (issued >= 3)
                    MBARRIER_WAIT_PARITY(sb + MB_OFF + 24 + sI * 8, (fI + 1) & 1);
                ISSUE_CC(j);
            }
            if (++sI == NSTAGE) { sI = 0; ++fI; }
            ++issued;
        }

        float accF[2][2][4], accG[2][2][4];
#pragma unroll
        for (int mi = 0; mi < 2; ++mi)
#pragma unroll
            for (int sN = 0; sN < 2; ++sN)
#pragma unroll
                for (int e = 0; e < 4; ++e) { accF[mi][sN][e] = 0.f; accG[mi][sN][e] = 0.f; }

        for (int cc = 0; cc < NCHUNK; ++cc) {
            MBARRIER_WAIT_PARITY(sb + MB_OFF + sC * 8, fC & 1);

            const int shift = (cc >= 4) ? dil : 0;
            const uint32_t sA  = sb + sC * STAGE_BYTES;
            const uint32_t sWF = sA + 16384;
            const uint32_t sWG = sA + 20480;
            const uint32_t akey = (uint32_t)((a_row - shift) & 7);

#pragma unroll
            for (int ks = 0; ks < 4; ++ks) {
                const uint32_t qa = (((uint32_t)(ks * 2) + a_q0) ^ akey) * 16;
                uint32_t aT[2][4], bF[4], bG[4];
                ldsm4(aT[0], sA + aoff0 + qa);
                ldsm4(aT[1], sA + aoff1 + qa);
                ldsm4(bF, sWF + boff + qbv[ks]);
                ldsm4(bG, sWG + boff + qbv[ks]);
#pragma unroll
                for (int mi = 0; mi < 2; ++mi)
#pragma unroll
                    for (int sN = 0; sN < 2; ++sN) {
                        mma16816(accF[mi][sN], aT[mi], &bF[sN * 2]);
                        mma16816(accG[mi][sN], aT[mi], &bG[sN * 2]);
                    }
            }

            if (lane == 0) MBARRIER_ARRIVE(sb + MB_OFF + 24 + sC * 8);
            if (cc + 3 < NCHUNK) {
                if (lane == 0 && wid == cc) {
                    MBARRIER_WAIT_PARITY(sb + MB_OFF + 24 + sI * 8, (fI + 1) & 1);
                    ISSUE_CC(cc + 3);
                }
                if (++sI == NSTAGE) { sI = 0; ++fI; }
                ++issued;
            }
            if (++sC == NSTAGE) { sC = 0; ++fC; }
        }
#undef ISSUE_CC

        __syncthreads();   // all warps done before smem reuse as z tile

        // ---- epilogue: z tile [t][c] (stride 36), MUFU activations ---------
        float* zs = reinterpret_cast<float*>(smem);   // 128 x 36 f32
        {
            const int g  = lane >> 2;
            const int tg = lane & 3;
            float fbv[2][2], gbv[2][2];
#pragma unroll
            for (int sN = 0; sN < 2; ++sN)
#pragma unroll
                for (int p = 0; p < 2; ++p) {
                    int cout = cout0 + n0 + sN * 8 + 2 * tg + p;
                    fbv[sN][p] = __ldg(fb + cout);
                    gbv[sN][p] = __ldg(gb + cout);
                }
#pragma unroll
            for (int mi = 0; mi < 2; ++mi)
#pragma unroll
                for (int sN = 0; sN < 2; ++sN)
#pragma unroll
                    for (int e = 0; e < 4; ++e) {
                        int t_loc = m0 + mi * 16 + g + (e >> 1) * 8;
                        int c_loc = n0 + sN * 8 + 2 * tg + (e & 1);
                        float F = accF[mi][sN][e] + fbv[sN][e & 1];
                        float G = accG[mi][sN][e] + gbv[sN][e & 1];
                        float th = 1.0f - __fdividef(2.0f, __expf(2.0f * F) + 1.0f);
                        float sg = __fdividef(1.0f, 1.0f + __expf(-G));
                        zs[t_loc * 36 + c_loc] = th * sg;
                    }
        }
        __syncthreads();

        // Y planes: swizzled quad stores
        const int kc = cout0 >> 6;
        const int qb0 = (cout0 & 32) >> 3;   // 0 or 4
#pragma unroll
        for (int i = 0; i < 2; ++i) {
            int iid = tid + i * 256;          // 512 total
            int q8 = iid & 3, t = iid >> 2;
            const float* zr = zs + t * 36 + q8 * 8;
            float4 z0 = reinterpret_cast<const float4*>(zr)[0];
            float4 z1 = reinterpret_cast<const float4*>(zr)[1];
            float zv[8] = { z0.x, z0.y, z0.z, z0.w, z1.x, z1.y, z1.z, z1.w };
            uint32_t pk[4];
#pragma unroll
            for (int p = 0; p < 4; ++p) {
                __half h0 = __float2half_rn(zv[2 * p]);
                __half h1 = __float2half_rn(zv[2 * p + 1]);
                pk[p] = (uint32_t)__half_as_ushort(h0) | ((uint32_t)__half_as_ushort(h1) << 16);
            }
            int tgl = t0 + t;
            int swq = (qb0 + q8) ^ (tgl & 7);
            __half* dst = Y + (((size_t)b * 4 + kc) * PROWS + GUARD + tgl) * 64 + swq * 8;
            *reinterpret_cast<uint4*>(dst) = make_uint4(pk[0], pk[1], pk[2], pk[3]);
        }
        // Zout: [b][c][t] f32
        const size_t zb = (size_t)b * CHAN * TLEN;
#pragma unroll
        for (int i = 0; i < 16; ++i) {
            int iid = tid + i * 256;          // 4096 total
            int t = iid & 127, cl = iid >> 7;
            float z = zs[t * 36 + cl];
            size_t o = zb + (size_t)(cout0 + cl) * TLEN + t0 + t;
            if (first) Zout[o] = z;
            else       Zout[o] += z;
        }

        // ---- publish: release this tile ------------------------------------
        __syncthreads();
        __threadfence();
        if (tid == 0) atomicAdd(&g_ready[l][b][T], 1);
    }   // tile loop
}

// ---------------- launch ----------------------------------------------------
extern "C" void kernel_launch(void* const* d_in, const int* in_sizes, int n_in,
                              void* d_out, int out_size) {
    const float* ys = (const float*)d_in[0];
    const float* fw = (const float*)d_in[1];
    const float* fb = (const float*)d_in[2];
    const float* gw = (const float*)d_in[3];
    const float* gb = (const float*)d_in[4];
    float* out = (float*)d_out;

    __half *xA, *xB, *wh;
    cudaGetSymbolAddress((void**)&xA, g_xA);
    cudaGetSymbolAddress((void**)&xB, g_xB);
    cudaGetSymbolAddress((void**)&wh, g_w2);

    cudaFuncSetAttribute(wavenet_persistent,
                         cudaFuncAttributeMaxDynamicSharedMemorySize, SM_TOTAL);
    int nb = 0, smc = 0;
    cudaOccupancyMaxActiveBlocksPerMultiprocessor(&nb, wavenet_persistent, 256, SM_TOTAL);
    cudaDeviceGetAttribute(&smc, cudaDevAttrMultiProcessorCount, 0);
    if (nb < 1) nb = 1;
    const int ncta = nb * smc;

    init_sync<<<(NLAYERS * BATCH * 32 + 255) / 256, 256>>>();
    {
        const size_t gz = (size_t)2 * BATCH * 4 * GUARD * 64;
        zero_guards<<<(int)((gz + 255) / 256), 256>>>();
        const int total = NLAYERS * 2 * 8 * 256 * 64;
        prep_weights<<<(total + 255) / 256, 256>>>(fw, gw);
        dim3 tg(TLEN / 32, CHAN / 32, BATCH);
        prep_input<<<tg, dim3(32, 8)>>>(ys);
    }

    wavenet_persistent<<<ncta, 256, SM_TOTAL>>>(xA, xB, wh, fb, gb, out);
}

// round 14
// speedup vs baseline: 1.0711x; 1.0711x over previous
#include <cuda_runtime.h>
#include <cuda_fp16.h>
#include <cstdint>
#include <math.h>

#define BATCH 16
#define CHAN  256
#define TLEN  4096
#define NLAYERS 8
#define NCHUNK 8                         // 8 chunks of k=64
#define GUARD 128
#define PROWS (GUARD + TLEN)             // 4224 rows per plane
#define PLANE ((size_t)PROWS * 64)       // halfs per (b,kc) plane (64-ch rows)
#define XBUF  ((size_t)BATCH * 4 * PLANE)
#define NTILES 4096                      // 32 t-tiles x 8 cout-blocks x 16 batch

// ---------------- device scratch -------------------------------------------
__device__ __align__(128) __half g_xA[XBUF];
__device__ __align__(128) __half g_xB[XBUF];
// W: [l][chunk8][cb8][fg2][32cout][64k], 8-quad swizzled by cout
__device__ __align__(128) __half g_w2[(size_t)NLAYERS * 8 * 8 * 2 * 32 * 64];
// persistent-kernel sync state (re-zeroed each launch)
__device__ int g_counter[NLAYERS];
__device__ int g_arrive[NLAYERS];

// ---------------- smem geometry --------------------------------------------
#define STAGE_BYTES 24576
#define STAGE_TX    24576
#define NSTAGE 3
#define MB_OFF (NSTAGE * STAGE_BYTES)       // 73728; full[3] then empty[3]
#define SM_TOTAL (MB_OFF + 64)              // 73792 dynamic

// ---------------- asm helpers ----------------------------------------------
__device__ __forceinline__ uint32_t smem_u32(const void* p) {
    uint32_t a;
    asm("{ .reg .u64 t; cvta.to.shared.u64 t, %1; cvt.u32.u64 %0, t; }" : "=r"(a) : "l"(p));
    return a;
}
#define MBARRIER_INIT(mbar, cnt) \
    asm volatile("mbarrier.init.shared.b64 [%0], %1;" :: "r"((uint32_t)(mbar)), "r"((uint32_t)(cnt)) : "memory")
#define MBARRIER_EXPECT_TX(mbar, tx) \
    asm volatile("mbarrier.arrive.expect_tx.shared.b64 _, [%0], %1;" :: "r"((uint32_t)(mbar)), "r"((uint32_t)(tx)) : "memory")
#define MBARRIER_ARRIVE(mbar) \
    asm volatile("mbarrier.arrive.shared.b64 _, [%0];" :: "r"((uint32_t)(mbar)) : "memory")
#define MBARRIER_WAIT_PARITY(mbar, par) do { \
    uint32_t _m = (uint32_t)(mbar); uint32_t _p = (uint32_t)(par); uint32_t _d; \
    asm volatile("{\n\t.reg .pred p;\n\tmbarrier.try_wait.parity.acquire.cta.shared::cta.b64 p, [%1], %2;\n\tselp.b32 %0,1,0,p;\n\t}" \
        : "=r"(_d) : "r"(_m), "r"(_p) : "memory"); \
    if (!_d) { \
        asm volatile("{\n\t.reg .pred P1;\n\tWL_%=:\n\tmbarrier.try_wait.parity.acquire.cta.shared::cta.b64 P1, [%0], %1, 0x989680;\n\t@P1 bra.uni WD_%=;\n\tbra.uni WL_%=;\n\tWD_%=:\n\t}" \
            :: "r"(_m), "r"(_p) : "memory"); \
    } } while (0)
__device__ __forceinline__ void bulk_ld(uint32_t dst, const void* src, uint32_t bytes, uint32_t mbar) {
    asm volatile("cp.async.bulk.shared::cluster.global.mbarrier::complete_tx::bytes [%0], [%1], %2, [%3];"
                 :: "r"(dst), "l"(src), "r"(bytes), "r"(mbar) : "memory");
}
__device__ __forceinline__ void ldsm4(uint32_t* r, uint32_t addr) {
    asm volatile("ldmatrix.sync.aligned.m8n8.x4.shared.b16 {%0,%1,%2,%3}, [%4];"
                 : "=r"(r[0]), "=r"(r[1]), "=r"(r[2]), "=r"(r[3]) : "r"(addr));
}
__device__ __forceinline__ void mma16816(float* d, const uint32_t* a, const uint32_t* b) {
    asm volatile("mma.sync.aligned.m16n8k16.row.col.f32.f16.f16.f32 "
                 "{%0,%1,%2,%3}, {%4,%5,%6,%7}, {%8,%9}, {%0,%1,%2,%3};"
                 : "+f"(d[0]), "+f"(d[1]), "+f"(d[2]), "+f"(d[3])
                 : "r"(a[0]), "r"(a[1]), "r"(a[2]), "r"(a[3]), "r"(b[0]), "r"(b[1]));
}

// ---------------- prep kernels ---------------------------------------------
__global__ void init_sync() {
    if (threadIdx.x < NLAYERS) {
        g_counter[threadIdx.x] = 0;
        g_arrive[threadIdx.x] = 0;
    }
}

__global__ void zero_guards() {
    const size_t per = (size_t)BATCH * 4 * GUARD * 64;    // 524288
    size_t i = (size_t)blockIdx.x * blockDim.x + threadIdx.x;
    if (i >= 2 * per) return;
    int arr = (int)(i / per);
    size_t r = i % per;
    size_t plane_i = r / (GUARD * 64);
    size_t within  = r % (GUARD * 64);
    __half* p = arr ? g_xB : g_xA;
    p[plane_i * PLANE + within] = __ushort_as_half(0);
}

// w[l][cout][cin][tap] -> g_w2[l][ch][cb][fg][co32][64k], swizzle q^(cout&7)
__global__ void prep_weights(const float* __restrict__ fw, const float* __restrict__ gw) {
    int idx = blockIdx.x * blockDim.x + threadIdx.x;
    const int total = NLAYERS * 2 * 8 * 256 * 64;
    if (idx >= total) return;
    int kk   = idx & 63;
    int cout = (idx >> 6) & 255;
    int ch   = (idx >> 14) & 7;
    int fg   = (idx >> 17) & 1;
    int l    = idx >> 18;
    const float* w = fg ? gw : fw;
    int cin = (ch & 3) * 64 + kk;
    int tap = (ch < 4) ? 1 : 0;    // first 4 chunks = current sample
    float v = w[(((size_t)l * CHAN + cout) * CHAN + cin) * 2 + tap];
    int pos = (((kk >> 3) ^ (cout & 7)) << 3) | (kk & 7);
    size_t o = (((((size_t)l * 8 + ch) * 8 + (cout >> 5)) * 2 + fg) * 32 + (cout & 31)) * 64 + pos;
    g_w2[o] = __float2half_rn(v);
}

// ys [b][c][t] f32 -> swizzled planes, fp16
__global__ void prep_input(const float* __restrict__ ys) {
    __shared__ float tile[32][33];
    const int b  = blockIdx.z;
    const int c0 = blockIdx.y * 32;
    const int t0 = blockIdx.x * 32;
    const int tx = threadIdx.x, ty = threadIdx.y;   // 32 x 8
#pragma unroll
    for (int i = 0; i < 32; i += 8)
        tile[ty + i][tx] = ys[((size_t)b * CHAN + c0 + ty + i) * TLEN + t0 + tx];
    __syncthreads();
    const int kc = c0 >> 6;
    const int qbase = (c0 & 32) >> 3;    // 0 or 4
#pragma unroll
    for (int i = 0; i < 32; i += 8) {
        int t = t0 + ty + i;
        int pos = (((qbase + (tx >> 3)) ^ (t & 7)) << 3) | (tx & 7);
        size_t o = (((size_t)b * 4 + kc) * PROWS + GUARD + t) * 64 + pos;
        g_xA[o] = __float2half_rn(tile[tx][ty + i]);
    }
}

// ---------------- persistent fused 8-layer kernel ----------------------------
__global__ __launch_bounds__(256, 3)
void wavenet_persistent(__half* __restrict__ xAp, __half* __restrict__ xBp,
                        const __half* __restrict__ Wbase,
                        const float* __restrict__ fbase,
                        const float* __restrict__ gbase,
                        float* __restrict__ Zout, int nCTA)
{
    extern __shared__ char smem[];
    __shared__ int s_tile;
    const uint32_t sb = smem_u32(smem);
    const int tid  = threadIdx.x;
    const int wid  = tid >> 5;
    const int lane = tid & 31;

    if (tid == 0) {
#pragma unroll
        for (int s = 0; s < NSTAGE; ++s) {
            MBARRIER_INIT(sb + MB_OFF + s * 8, 1);            // full: tx-based
            MBARRIER_INIT(sb + MB_OFF + 24 + s * 8, 8);       // empty: 8 warp arrivals
        }
    }
    __syncthreads();

    // ---- loop-invariant ldsm addressing ----
    const int m0 = (wid & 3) * 32;       // t within tile
    const int n0 = (wid >> 2) * 16;      // cout within tile (0 or 16)
    const int a_row = lane & 15;
    const uint32_t a_q0  = (uint32_t)(lane >> 4);
    const int b_row = ((lane >> 4) * 8) + (lane & 7);
    const uint32_t b_q0  = (uint32_t)((lane >> 3) & 1);
    const uint32_t aoff0 = (uint32_t)((m0 + a_row) * 128);
    const uint32_t aoff1 = aoff0 + 16 * 128;
    const uint32_t boff  = (uint32_t)((n0 + b_row) * 128);
    uint32_t qbv[4];
#pragma unroll
    for (int ks = 0; ks < 4; ++ks)
        qbv[ks] = (((uint32_t)(ks * 2) + b_q0) ^ (uint32_t)(b_row & 7)) * 16;

    // rolling pipeline state (continuous across tiles and layers)
    int sC = 0, fC = 0;        // consume: stage, phase
    int sI = 0, fI = 0;        // issue:   stage, phase
    int issued = 0;

    for (int l = 0; l < NLAYERS; ++l) {
        const __half* X = (l & 1) ? xBp : xAp;
        __half*       Y = (l & 1) ? xAp : xBp;
        const __half* Wl = Wbase + (size_t)l * 8 * 8 * 2 * 32 * 64;
        const float*  fb = fbase + l * CHAN;
        const float*  gb = gbase + l * CHAN;
        const int dil   = 1 << l;
        const int first = (l == 0);
        const int last  = (l == NLAYERS - 1);

        while (true) {
            if (tid == 0) s_tile = atomicAdd(&g_counter[l], 1);
            __syncthreads();
            const int tile = s_tile;
            if (tile >= NTILES) break;

            const int t0    = (tile & 31) << 7;
            const int cb    = (tile >> 5) & 7;
            const int b     = tile >> 8;
            const int cout0 = cb << 5;
            const __half* Xb = X + (size_t)b * 4 * PLANE;

#define ISSUE_CC(CC) do {                                                        \
            uint32_t _mb = sb + MB_OFF + sI * 8;                                 \
            uint32_t _st = sb + sI * STAGE_BYTES;                                \
            int _sh = ((CC) >= 4) ? dil : 0;                                     \
            int _kc = (CC) & 3;                                                  \
            MBARRIER_EXPECT_TX(_mb, STAGE_TX);                                   \
            bulk_ld(_st,         Xb + ((size_t)_kc * PROWS + GUARD + t0 - _sh) * 64, 16384, _mb); \
            bulk_ld(_st + 16384, Wl + ((size_t)(CC) * 8 + cb) * 4096, 8192, _mb); \
        } while (0)

            // prologue: 3 chunk issues (tid 0), counters advance uniformly
#pragma unroll
            for (int j = 0; j < 3; ++j) {
                if (tid == 0) {
                    if (issued >= 3)
                        MBARRIER_WAIT_PARITY(sb + MB_OFF + 24 + sI * 8, (fI + 1) & 1);
                    ISSUE_CC(j);
                }
                if (++sI == NSTAGE) { sI = 0; ++fI; }
                ++issued;
            }

            float accF[2][2][4], accG[2][2][4];
#pragma unroll
            for (int mi = 0; mi < 2; ++mi)
#pragma unroll
                for (int sN = 0; sN < 2; ++sN)
#pragma unroll
                    for (int e = 0; e < 4; ++e) { accF[mi][sN][e] = 0.f; accG[mi][sN][e] = 0.f; }

            for (int cc = 0; cc < NCHUNK; ++cc) {
                MBARRIER_WAIT_PARITY(sb + MB_OFF + sC * 8, fC & 1);

                const int shift = (cc >= 4) ? dil : 0;
                const uint32_t sA  = sb + sC * STAGE_BYTES;
                const uint32_t sWF = sA + 16384;
                const uint32_t sWG = sA + 20480;
                const uint32_t akey = (uint32_t)((a_row - shift) & 7);

#pragma unroll
                for (int ks = 0; ks < 4; ++ks) {
                    const uint32_t qa = (((uint32_t)(ks * 2) + a_q0) ^ akey) * 16;
                    uint32_t aT[2][4], bF[4], bG[4];
                    ldsm4(aT[0], sA + aoff0 + qa);
                    ldsm4(aT[1], sA + aoff1 + qa);
                    ldsm4(bF, sWF + boff + qbv[ks]);
                    ldsm4(bG, sWG + boff + qbv[ks]);
#pragma unroll
                    for (int mi = 0; mi < 2; ++mi)
#pragma unroll
                        for (int sN = 0; sN < 2; ++sN) {
                            mma16816(accF[mi][sN], aT[mi], &bF[sN * 2]);
                            mma16816(accG[mi][sN], aT[mi], &bG[sN * 2]);
                        }
                }

                if (lane == 0) MBARRIER_ARRIVE(sb + MB_OFF + 24 + sC * 8);
                if (cc + 3 < NCHUNK) {
                    if (lane == 0 && wid == cc) {
                        MBARRIER_WAIT_PARITY(sb + MB_OFF + 24 + sI * 8, (fI + 1) & 1);
                        ISSUE_CC(cc + 3);
                    }
                    if (++sI == NSTAGE) { sI = 0; ++fI; }
                    ++issued;
                }
                if (++sC == NSTAGE) { sC = 0; ++fC; }
            }
#undef ISSUE_CC

            __syncthreads();   // all warps done before smem reuse as z tile

            // ---- epilogue: z tile [t][c] (stride 36), MUFU activations ------
            float* zs = reinterpret_cast<float*>(smem);   // 128 x 36 f32
            {
                const int g  = lane >> 2;
                const int tg = lane & 3;
                float fbv[2][2], gbv[2][2];
#pragma unroll
                for (int sN = 0; sN < 2; ++sN)
#pragma unroll
                    for (int p = 0; p < 2; ++p) {
                        int cout = cout0 + n0 + sN * 8 + 2 * tg + p;
                        fbv[sN][p] = __ldg(fb + cout);
                        gbv[sN][p] = __ldg(gb + cout);
                    }
#pragma unroll
                for (int mi = 0; mi < 2; ++mi)
#pragma unroll
                    for (int sN = 0; sN < 2; ++sN)
#pragma unroll
                        for (int e = 0; e < 4; ++e) {
                            int t_loc = m0 + mi * 16 + g + (e >> 1) * 8;
                            int c_loc = n0 + sN * 8 + 2 * tg + (e & 1);
                            float F = accF[mi][sN][e] + fbv[sN][e & 1];
                            float G = accG[mi][sN][e] + gbv[sN][e & 1];
                            // tanh(F) = 1 - 2/(e^{2F}+1); sigmoid(G) = 1/(1+e^{-G})
                            float th = 1.0f - __fdividef(2.0f, __expf(2.0f * F) + 1.0f);
                            float sg = __fdividef(1.0f, 1.0f + __expf(-G));
                            zs[t_loc * 36 + c_loc] = th * sg;
                        }
            }
            __syncthreads();

            // Y planes: swizzled quad stores (skipped on last layer — unused)
            if (!last) {
                const int kc = cout0 >> 6;
                const int qb0 = (cout0 & 32) >> 3;   // 0 or 4
#pragma unroll
                for (int i = 0; i < 2; ++i) {
                    int id = tid + i * 256;          // 512 total
                    int q8 = id & 3, t = id >> 2;
                    const float* zr = zs + t * 36 + q8 * 8;
                    float4 z0 = reinterpret_cast<const float4*>(zr)[0];
                    float4 z1 = reinterpret_cast<const float4*>(zr)[1];
                    float zv[8] = { z0.x, z0.y, z0.z, z0.w, z1.x, z1.y, z1.z, z1.w };
                    uint32_t pk[4];
#pragma unroll
                    for (int p = 0; p < 4; ++p) {
                        __half h0 = __float2half_rn(zv[2 * p]);
                        __half h1 = __float2half_rn(zv[2 * p + 1]);
                        pk[p] = (uint32_t)__half_as_ushort(h0) | ((uint32_t)__half_as_ushort(h1) << 16);
                    }
                    int tgl = t0 + t;
                    int swq = (qb0 + q8) ^ (tgl & 7);
                    __half* dst = Y + (((size_t)b * 4 + kc) * PROWS + GUARD + tgl) * 64 + swq * 8;
                    *reinterpret_cast<uint4*>(dst) = make_uint4(pk[0], pk[1], pk[2], pk[3]);
                }
            }
            // Zout: [b][c][t] f32
            const size_t zb = (size_t)b * CHAN * TLEN;
#pragma unroll
            for (int i = 0; i < 16; ++i) {
                int id = tid + i * 256;          // 4096 total
                int t = id & 127, cl = id >> 7;
                float z = zs[t * 36 + cl];
                size_t o = zb + (size_t)(cout0 + cl) * TLEN + t0 + t;
                if (first) Zout[o] = z;
                else       Zout[o] += z;
            }
        }   // tile loop

        // ---- inter-layer global barrier (skipped after the final layer) -----
        if (!last) {
            if (tid == 0) {
                __threadfence();
                atomicAdd(&g_arrive[l], 1);
                while (*(volatile int*)&g_arrive[l] < nCTA) __nanosleep(64);
            }
            __syncthreads();
            __threadfence();
        }
    }   // layer loop
}

// ---------------- launch ----------------------------------------------------
extern "C" void kernel_launch(void* const* d_in, const int* in_sizes, int n_in,
                              void* d_out, int out_size) {
    const float* ys = (const float*)d_in[0];
    const float* fw = (const float*)d_in[1];
    const float* fb = (const float*)d_in[2];
    const float* gw = (const float*)d_in[3];
    const float* gb = (const float*)d_in[4];
    float* out = (float*)d_out;

    __half *xA, *xB, *wh;
    cudaGetSymbolAddress((void**)&xA, g_xA);
    cudaGetSymbolAddress((void**)&xB, g_xB);
    cudaGetSymbolAddress((void**)&wh, g_w2);

    cudaFuncSetAttribute(wavenet_persistent,
                         cudaFuncAttributeMaxDynamicSharedMemorySize, SM_TOTAL);
    int nb = 0, smc = 0;
    cudaOccupancyMaxActiveBlocksPerMultiprocessor(&nb, wavenet_persistent, 256, SM_TOTAL);
    cudaDeviceGetAttribute(&smc, cudaDevAttrMultiProcessorCount, 0);
    if (nb < 1) nb = 1;
    const int ncta = nb * smc;

    init_sync<<<1, 32>>>();
    {
        const size_t gz = (size_t)2 * BATCH * 4 * GUARD * 64;
        zero_guards<<<(int)((gz + 255) / 256), 256>>>();
        const int total = NLAYERS * 2 * 8 * 256 * 64;
        prep_weights<<<(total + 255) / 256, 256>>>(fw, gw);
        dim3 tg(TLEN / 32, CHAN / 32, BATCH);
        prep_input<<<tg, dim3(32, 8)>>>(ys);
    }

    wavenet_persistent<<<ncta, 256, SM_TOTAL>>>(xA, xB, wh, fb, gb, out, ncta);
}

// round 16
// speedup vs baseline: 1.3770x; 1.2856x over previous
#include <cuda_runtime.h>
#include <cuda_fp16.h>
#include <cstdint>
#include <math.h>

#define BATCH 16
#define CHAN  256
#define TLEN  4096
#define NLAYERS 8
#define NCHUNK 8                         // 8 chunks of k=64
#define GUARD 128
#define PROWS (GUARD + TLEN)             // 4224 rows per plane
#define PLANE ((size_t)PROWS * 64)       // halfs per (b,kc) plane (64-ch rows)
#define XBUF  ((size_t)BATCH * 4 * PLANE)
#define NTILES 4096                      // 32 t-tiles x 8 cout-blocks x 16 batch

// ---------------- device scratch -------------------------------------------
__device__ __align__(128) __half g_xA[XBUF];
__device__ __align__(128) __half g_xB[XBUF];
// W: [l][chunk8][cb8][fg2][32cout][64k], 8-quad swizzled by cout
__device__ __align__(128) __half g_w2[(size_t)NLAYERS * 8 * 8 * 2 * 32 * 64];
// persistent-kernel sync state (re-zeroed each launch)
__device__ int g_counter[NLAYERS];
__device__ int g_arrive[NLAYERS];

// ---------------- smem geometry --------------------------------------------
#define STAGE_BYTES 24576
#define STAGE_TX    24576
#define NSTAGE 3
#define MB_OFF (NSTAGE * STAGE_BYTES)       // 73728; full[3] then empty[3]
#define SM_TOTAL (MB_OFF + 64)              // 73792 dynamic

// ---------------- asm helpers ----------------------------------------------
__device__ __forceinline__ uint32_t smem_u32(const void* p) {
    uint32_t a;
    asm("{ .reg .u64 t; cvta.to.shared.u64 t, %1; cvt.u32.u64 %0, t; }" : "=r"(a) : "l"(p));
    return a;
}
#define MBARRIER_INIT(mbar, cnt) \
    asm volatile("mbarrier.init.shared.b64 [%0], %1;" :: "r"((uint32_t)(mbar)), "r"((uint32_t)(cnt)) : "memory")
#define MBARRIER_EXPECT_TX(mbar, tx) \
    asm volatile("mbarrier.arrive.expect_tx.shared.b64 _, [%0], %1;" :: "r"((uint32_t)(mbar)), "r"((uint32_t)(tx)) : "memory")
#define MBARRIER_ARRIVE(mbar) \
    asm volatile("mbarrier.arrive.shared.b64 _, [%0];" :: "r"((uint32_t)(mbar)) : "memory")
#define MBARRIER_WAIT_PARITY(mbar, par) do { \
    uint32_t _m = (uint32_t)(mbar); uint32_t _p = (uint32_t)(par); uint32_t _d; \
    asm volatile("{\n\t.reg .pred p;\n\tmbarrier.try_wait.parity.acquire.cta.shared::cta.b64 p, [%1], %2;\n\tselp.b32 %0,1,0,p;\n\t}" \
        : "=r"(_d) : "r"(_m), "r"(_p) : "memory"); \
    if (!_d) { \
        asm volatile("{\n\t.reg .pred P1;\n\tWL_%=:\n\tmbarrier.try_wait.parity.acquire.cta.shared::cta.b64 P1, [%0], %1, 0x989680;\n\t@P1 bra.uni WD_%=;\n\tbra.uni WL_%=;\n\tWD_%=:\n\t}" \
            :: "r"(_m), "r"(_p) : "memory"); \
    } } while (0)
__device__ __forceinline__ void bulk_ld(uint32_t dst, const void* src, uint32_t bytes, uint32_t mbar) {
    asm volatile("cp.async.bulk.shared::cluster.global.mbarrier::complete_tx::bytes [%0], [%1], %2, [%3];"
                 :: "r"(dst), "l"(src), "r"(bytes), "r"(mbar) : "memory");
}
__device__ __forceinline__ void ldsm4(uint32_t* r, uint32_t addr) {
    asm volatile("ldmatrix.sync.aligned.m8n8.x4.shared.b16 {%0,%1,%2,%3}, [%4];"
                 : "=r"(r[0]), "=r"(r[1]), "=r"(r[2]), "=r"(r[3]) : "r"(addr));
}
__device__ __forceinline__ void mma16816(float* d, const uint32_t* a, const uint32_t* b) {
    asm volatile("mma.sync.aligned.m16n8k16.row.col.f32.f16.f16.f32 "
                 "{%0,%1,%2,%3}, {%4,%5,%6,%7}, {%8,%9}, {%0,%1,%2,%3};"
                 : "+f"(d[0]), "+f"(d[1]), "+f"(d[2]), "+f"(d[3])
                 : "r"(a[0]), "r"(a[1]), "r"(a[2]), "r"(a[3]), "r"(b[0]), "r"(b[1]));
}
__device__ __forceinline__ void red_add_f32(float* p, float v) {
    asm volatile("red.global.add.f32 [%0], %1;" :: "l"(p), "f"(v) : "memory");
}

// ---------------- prep kernels ---------------------------------------------
__global__ void init_sync() {
    if (threadIdx.x < NLAYERS) {
        g_counter[threadIdx.x] = 0;
        g_arrive[threadIdx.x] = 0;
    }
}

__global__ void zero_guards() {
    const size_t per = (size_t)BATCH * 4 * GUARD * 64;    // 524288
    size_t i = (size_t)blockIdx.x * blockDim.x + threadIdx.x;
    if (i >= 2 * per) return;
    int arr = (int)(i / per);
    size_t r = i % per;
    size_t plane_i = r / (GUARD * 64);
    size_t within  = r % (GUARD * 64);
    __half* p = arr ? g_xB : g_xA;
    p[plane_i * PLANE + within] = __ushort_as_half(0);
}

// w[l][cout][cin][tap] -> g_w2[l][ch][cb][fg][co32][64k], swizzle q^(cout&7)
__global__ void prep_weights(const float* __restrict__ fw, const float* __restrict__ gw) {
    int idx = blockIdx.x * blockDim.x + threadIdx.x;
    const int total = NLAYERS * 2 * 8 * 256 * 64;
    if (idx >= total) return;
    int kk   = idx & 63;
    int cout = (idx >> 6) & 255;
    int ch   = (idx >> 14) & 7;
    int fg   = (idx >> 17) & 1;
    int l    = idx >> 18;
    const float* w = fg ? gw : fw;
    int cin = (ch & 3) * 64 + kk;
    int tap = (ch < 4) ? 1 : 0;    // first 4 chunks = current sample
    float v = w[(((size_t)l * CHAN + cout) * CHAN + cin) * 2 + tap];
    int pos = (((kk >> 3) ^ (cout & 7)) << 3) | (kk & 7);
    size_t o = (((((size_t)l * 8 + ch) * 8 + (cout >> 5)) * 2 + fg) * 32 + (cout & 31)) * 64 + pos;
    g_w2[o] = __float2half_rn(v);
}

// ys [b][c][t] f32 -> swizzled planes, fp16
__global__ void prep_input(const float* __restrict__ ys) {
    __shared__ float tile[32][33];
    const int b  = blockIdx.z;
    const int c0 = blockIdx.y * 32;
    const int t0 = blockIdx.x * 32;
    const int tx = threadIdx.x, ty = threadIdx.y;   // 32 x 8
#pragma unroll
    for (int i = 0; i < 32; i += 8)
        tile[ty + i][tx] = ys[((size_t)b * CHAN + c0 + ty + i) * TLEN + t0 + tx];
    __syncthreads();
    const int kc = c0 >> 6;
    const int qbase = (c0 & 32) >> 3;    // 0 or 4
#pragma unroll
    for (int i = 0; i < 32; i += 8) {
        int t = t0 + ty + i;
        int pos = (((qbase + (tx >> 3)) ^ (t & 7)) << 3) | (tx & 7);
        size_t o = (((size_t)b * 4 + kc) * PROWS + GUARD + t) * 64 + pos;
        g_xA[o] = __float2half_rn(tile[tx][ty + i]);
    }
}

// ---------------- persistent fused 8-layer kernel ----------------------------
__global__ __launch_bounds__(256, 3)
void wavenet_persistent(__half* __restrict__ xAp, __half* __restrict__ xBp,
                        const __half* __restrict__ Wbase,
                        const float* __restrict__ fbase,
                        const float* __restrict__ gbase,
                        float* __restrict__ Zout, int nCTA)
{
    extern __shared__ char smem[];
    __shared__ int s_tile;
    const uint32_t sb = smem_u32(smem);
    const int tid  = threadIdx.x;
    const int wid  = tid >> 5;
    const int lane = tid & 31;

    if (tid == 0) {
#pragma unroll
        for (int s = 0; s < NSTAGE; ++s) {
            MBARRIER_INIT(sb + MB_OFF + s * 8, 1);            // full: tx-based
            MBARRIER_INIT(sb + MB_OFF + 24 + s * 8, 8);       // empty: 8 warp arrivals
        }
    }
    __syncthreads();

    // ---- loop-invariant ldsm addressing ----
    const int m0 = (wid & 3) * 32;       // t within tile
    const int n0 = (wid >> 2) * 16;      // cout within tile (0 or 16)
    const int a_row = lane & 15;
    const uint32_t a_q0  = (uint32_t)(lane >> 4);
    const int b_row = ((lane >> 4) * 8) + (lane & 7);
    const uint32_t b_q0  = (uint32_t)((lane >> 3) & 1);
    const uint32_t aoff0 = (uint32_t)((m0 + a_row) * 128);
    const uint32_t aoff1 = aoff0 + 16 * 128;
    const uint32_t boff  = (uint32_t)((n0 + b_row) * 128);
    uint32_t qbv[4];
#pragma unroll
    for (int ks = 0; ks < 4; ++ks)
        qbv[ks] = (((uint32_t)(ks * 2) + b_q0) ^ (uint32_t)(b_row & 7)) * 16;

    // rolling pipeline state (continuous across tiles and layers)
    int sC = 0, fC = 0;        // consume: stage, phase
    int sI = 0, fI = 0;        // issue:   stage, phase
    int issued = 0;

    for (int l = 0; l < NLAYERS; ++l) {
        const __half* X = (l & 1) ? xBp : xAp;
        __half*       Y = (l & 1) ? xAp : xBp;
        const __half* Wl = Wbase + (size_t)l * 8 * 8 * 2 * 32 * 64;
        const float*  fb = fbase + l * CHAN;
        const float*  gb = gbase + l * CHAN;
        const int dil   = 1 << l;
        const int first = (l == 0);
        const int last  = (l == NLAYERS - 1);

        while (true) {
            if (tid == 0) s_tile = atomicAdd(&g_counter[l], 1);
            __syncthreads();
            const int tile = s_tile;
            if (tile >= NTILES) break;

            const int t0    = (tile & 31) << 7;
            const int cb    = (tile >> 5) & 7;
            const int b     = tile >> 8;
            const int cout0 = cb << 5;
            const __half* Xb = X + (size_t)b * 4 * PLANE;

#define ISSUE_CC(CC) do {                                                        \
            uint32_t _mb = sb + MB_OFF + sI * 8;                                 \
            uint32_t _st = sb + sI * STAGE_BYTES;                                \
            int _sh = ((CC) >= 4) ? dil : 0;                                     \
            int _kc = (CC) & 3;                                                  \
            MBARRIER_EXPECT_TX(_mb, STAGE_TX);                                   \
            bulk_ld(_st,         Xb + ((size_t)_kc * PROWS + GUARD + t0 - _sh) * 64, 16384, _mb); \
            bulk_ld(_st + 16384, Wl + ((size_t)(CC) * 8 + cb) * 4096, 8192, _mb); \
        } while (0)

            // prologue: 3 chunk issues (tid 0), counters advance uniformly
#pragma unroll
            for (int j = 0; j < 3; ++j) {
                if (tid == 0) {
                    if (issued >= 3)
                        MBARRIER_WAIT_PARITY(sb + MB_OFF + 24 + sI * 8, (fI + 1) & 1);
                    ISSUE_CC(j);
                }
                if (++sI == NSTAGE) { sI = 0; ++fI; }
                ++issued;
            }

            float accF[2][2][4], accG[2][2][4];
#pragma unroll
            for (int mi = 0; mi < 2; ++mi)
#pragma unroll
                for (int sN = 0; sN < 2; ++sN)
#pragma unroll
                    for (int e = 0; e < 4; ++e) { accF[mi][sN][e] = 0.f; accG[mi][sN][e] = 0.f; }

            for (int cc = 0; cc < NCHUNK; ++cc) {
                MBARRIER_WAIT_PARITY(sb + MB_OFF + sC * 8, fC & 1);

                const int shift = (cc >= 4) ? dil : 0;
                const uint32_t sA  = sb + sC * STAGE_BYTES;
                const uint32_t sWF = sA + 16384;
                const uint32_t sWG = sA + 20480;
                const uint32_t akey = (uint32_t)((a_row - shift) & 7);

#pragma unroll
                for (int ks = 0; ks < 4; ++ks) {
                    const uint32_t qa = (((uint32_t)(ks * 2) + a_q0) ^ akey) * 16;
                    uint32_t aT[2][4], bF[4], bG[4];
                    ldsm4(aT[0], sA + aoff0 + qa);
                    ldsm4(aT[1], sA + aoff1 + qa);
                    ldsm4(bF, sWF + boff + qbv[ks]);
                    ldsm4(bG, sWG + boff + qbv[ks]);
#pragma unroll
                    for (int mi = 0; mi < 2; ++mi)
#pragma unroll
                        for (int sN = 0; sN < 2; ++sN) {
                            mma16816(accF[mi][sN], aT[mi], &bF[sN * 2]);
                            mma16816(accG[mi][sN], aT[mi], &bG[sN * 2]);
                        }
                }

                if (lane == 0) MBARRIER_ARRIVE(sb + MB_OFF + 24 + sC * 8);
                if (cc + 3 < NCHUNK) {
                    if (lane == 0 && wid == cc) {
                        MBARRIER_WAIT_PARITY(sb + MB_OFF + 24 + sI * 8, (fI + 1) & 1);
                        ISSUE_CC(cc + 3);
                    }
                    if (++sI == NSTAGE) { sI = 0; ++fI; }
                    ++issued;
                }
                if (++sC == NSTAGE) { sC = 0; ++fC; }
            }
#undef ISSUE_CC

            __syncthreads();   // all warps done before smem reuse as z tile

            // ---- epilogue: z tile [t][c] (stride 36), MUFU activations ------
            float* zs = reinterpret_cast<float*>(smem);   // 128 x 36 f32
            {
                const int g  = lane >> 2;
                const int tg = lane & 3;
                float fbv[2][2], gbv[2][2];
#pragma unroll
                for (int sN = 0; sN < 2; ++sN)
#pragma unroll
                    for (int p = 0; p < 2; ++p) {
                        int cout = cout0 + n0 + sN * 8 + 2 * tg + p;
                        fbv[sN][p] = __ldg(fb + cout);
                        gbv[sN][p] = __ldg(gb + cout);
                    }
#pragma unroll
                for (int mi = 0; mi < 2; ++mi)
#pragma unroll
                    for (int sN = 0; sN < 2; ++sN)
#pragma unroll
                        for (int e = 0; e < 4; ++e) {
                            int t_loc = m0 + mi * 16 + g + (e >> 1) * 8;
                            int c_loc = n0 + sN * 8 + 2 * tg + (e & 1);
                            float F = accF[mi][sN][e] + fbv[sN][e & 1];
                            float G = accG[mi][sN][e] + gbv[sN][e & 1];
                            // tanh(F) = 1 - 2/(e^{2F}+1); sigmoid(G) = 1/(1+e^{-G})
                            float th = 1.0f - __fdividef(2.0f, __expf(2.0f * F) + 1.0f);
                            float sg = __fdividef(1.0f, 1.0f + __expf(-G));
                            zs[t_loc * 36 + c_loc] = th * sg;
                        }
            }
            __syncthreads();

            // Y planes: swizzled quad stores (skipped on last layer — unused)
            if (!last) {
                const int kc = cout0 >> 6;
                const int qb0 = (cout0 & 32) >> 3;   // 0 or 4
#pragma unroll
                for (int i = 0; i < 2; ++i) {
                    int id = tid + i * 256;          // 512 total
                    int q8 = id & 3, t = id >> 2;
                    const float* zr = zs + t * 36 + q8 * 8;
                    float4 z0 = reinterpret_cast<const float4*>(zr)[0];
                    float4 z1 = reinterpret_cast<const float4*>(zr)[1];
                    float zv[8] = { z0.x, z0.y, z0.z, z0.w, z1.x, z1.y, z1.z, z1.w };
                    uint32_t pk[4];
#pragma unroll
                    for (int p = 0; p < 4; ++p) {
                        __half h0 = __float2half_rn(zv[2 * p]);
                        __half h1 = __float2half_rn(zv[2 * p + 1]);
                        pk[p] = (uint32_t)__half_as_ushort(h0) | ((uint32_t)__half_as_ushort(h1) << 16);
                    }
                    int tgl = t0 + t;
                    int swq = (qb0 + q8) ^ (tgl & 7);
                    __half* dst = Y + (((size_t)b * 4 + kc) * PROWS + GUARD + tgl) * 64 + swq * 8;
                    *reinterpret_cast<uint4*>(dst) = make_uint4(pk[0], pk[1], pk[2], pk[3]);
                }
            }
            // Zout: [b][c][t] f32 — plain store on layer 0, REDG add afterwards
            const size_t zb = (size_t)b * CHAN * TLEN;
            if (first) {
#pragma unroll
                for (int i = 0; i < 16; ++i) {
                    int id = tid + i * 256;          // 4096 total
                    int t = id & 127, cl = id >> 7;
                    Zout[zb + (size_t)(cout0 + cl) * TLEN + t0 + t] = zs[t * 36 + cl];
                }
            } else {
#pragma unroll
                for (int i = 0; i < 16; ++i) {
                    int id = tid + i * 256;
                    int t = id & 127, cl = id >> 7;
                    red_add_f32(Zout + zb + (size_t)(cout0 + cl) * TLEN + t0 + t,
                                zs[t * 36 + cl]);
                }
            }
        }   // tile loop

        // ---- inter-layer global barrier (skipped after the final layer) -----
        if (!last) {
            if (tid == 0) {
                __threadfence();
                atomicAdd(&g_arrive[l], 1);
                while (*(volatile int*)&g_arrive[l] < nCTA) __nanosleep(64);
            }
            __syncthreads();
            __threadfence();
        }
    }   // layer loop
}

// ---------------- launch ----------------------------------------------------
extern "C" void kernel_launch(void* const* d_in, const int* in_sizes, int n_in,
                              void* d_out, int out_size) {
    const float* ys = (const float*)d_in[0];
    const float* fw = (const float*)d_in[1];
    const float* fb = (const float*)d_in[2];
    const float* gw = (const float*)d_in[3];
    const float* gb = (const float*)d_in[4];
    float* out = (float*)d_out;

    __half *xA, *xB, *wh;
    cudaGetSymbolAddress((void**)&xA, g_xA);
    cudaGetSymbolAddress((void**)&xB, g_xB);
    cudaGetSymbolAddress((void**)&wh, g_w2);

    cudaFuncSetAttribute(wavenet_persistent,
                         cudaFuncAttributeMaxDynamicSharedMemorySize, SM_TOTAL);
    int nb = 0, smc = 0;
    cudaOccupancyMaxActiveBlocksPerMultiprocessor(&nb, wavenet_persistent, 256, SM_TOTAL);
    cudaDeviceGetAttribute(&smc, cudaDevAttrMultiProcessorCount, 0);
    if (nb < 1) nb = 1;
    const int ncta = nb * smc;

    init_sync<<<1, 32>>>();
    {
        const size_t gz = (size_t)2 * BATCH * 4 * GUARD * 64;
        zero_guards<<<(int)((gz + 255) / 256), 256>>>();
        const int total = NLAYERS * 2 * 8 * 256 * 64;
        prep_weights<<<(total + 255) / 256, 256>>>(fw, gw);
        dim3 tg(TLEN / 32, CHAN / 32, BATCH);
        prep_input<<<tg, dim3(32, 8)>>>(ys);
    }

    wavenet_persistent<<<ncta, 256, SM_TOTAL>>>(xA, xB, wh, fb, gb, out, ncta);
}